// round 3
// baseline (speedup 1.0000x reference)
#include <cuda_runtime.h>
#include <math.h>

#define TTOK 2048
#define HDIM 2048
#define IDIM 4096
#define EEXP 8
#define KTOP 2
#define BM 128
#define BN 128
#define BK 16

// Scratch (device globals; allocation in kernel_launch is forbidden)
__device__ float g_tn[(size_t)TTOK * HDIM];          // normalized tokens, 16MB
__device__ int   g_cnt[EEXP];
__device__ int   g_off[EEXP];
__device__ int   g_tok[EEXP][TTOK];                  // token index per expert slot
__device__ float g_wt [EEXP][TTOK];                  // combine weight per expert slot
__device__ int   g_tok_e[TTOK][KTOP];
__device__ int   g_tok_p[TTOK][KTOP];
__device__ float g_g[(size_t)TTOK * KTOP * IDIM];    // gate preact, 64MB
__device__ float g_h[(size_t)TTOK * KTOP * IDIM];    // silu(g)*u,   64MB
__device__ float g_y[(size_t)TTOK * KTOP * HDIM];    // weighted down out, 32MB

__global__ void zero_cnt_kernel() {
    if (threadIdx.x < EEXP) g_cnt[threadIdx.x] = 0;
}

__global__ void prefix_kernel() {
    int r = 0;
    for (int e = 0; e < EEXP; e++) { g_off[e] = r; r += g_cnt[e]; }
}

// One block per token: RMSNorm + router logits + softmax + top-2 + compaction.
__global__ __launch_bounds__(256) void norm_route_kernel(
    const float* __restrict__ x,
    const float* __restrict__ norm_w,
    const float* __restrict__ router_w)
{
    int t   = blockIdx.x;
    int tid = threadIdx.x;
    __shared__ float s_tn[HDIM];
    __shared__ float s_red[8];
    __shared__ float s_logit[EEXP];

    const float* xr = x + (size_t)t * HDIM;
    float v[8];
    float ss = 0.f;
    #pragma unroll
    for (int i = 0; i < 8; i++) {
        float xv = xr[tid + i * 256];
        v[i] = xv;
        ss += xv * xv;
    }
    #pragma unroll
    for (int o = 16; o; o >>= 1) ss += __shfl_xor_sync(0xffffffffu, ss, o);
    if ((tid & 31) == 0) s_red[tid >> 5] = ss;
    __syncthreads();
    if (tid < 8) {
        float r = s_red[tid];
        #pragma unroll
        for (int o = 4; o; o >>= 1) r += __shfl_xor_sync(0xffu, r, o);
        if (tid == 0) s_red[0] = r;
    }
    __syncthreads();
    float inv = rsqrtf(s_red[0] * (1.0f / HDIM) + 1e-6f);
    #pragma unroll
    for (int i = 0; i < 8; i++) {
        int h = tid + i * 256;
        float tnv = v[i] * inv * norm_w[h];
        s_tn[h] = tnv;
        g_tn[(size_t)t * HDIM + h] = tnv;
    }
    __syncthreads();

    // 8 warps, warp e computes logit for expert e
    int e = tid >> 5, lane = tid & 31;
    float lg = 0.f;
    for (int h = lane; h < HDIM; h += 32) lg += s_tn[h] * router_w[h * EEXP + e];
    #pragma unroll
    for (int o = 16; o; o >>= 1) lg += __shfl_xor_sync(0xffffffffu, lg, o);
    if (lane == 0) s_logit[e] = lg;
    __syncthreads();

    if (tid == 0) {
        float mx = -1e30f;
        #pragma unroll
        for (int i = 0; i < EEXP; i++) mx = fmaxf(mx, s_logit[i]);
        float p[EEXP];
        #pragma unroll
        for (int i = 0; i < EEXP; i++) p[i] = expf(s_logit[i] - mx);
        // top-2 (softmax denominator cancels in the K-normalization)
        int i0 = 0;
        #pragma unroll
        for (int i = 1; i < EEXP; i++) if (p[i] > p[i0]) i0 = i;
        int i1 = (i0 == 0) ? 1 : 0;
        #pragma unroll
        for (int i = 0; i < EEXP; i++) {
            if (i == i0) continue;
            if (p[i] > p[i1]) i1 = i;
        }
        float v0 = p[i0], v1 = p[i1];
        float wsum = v0 + v1;
        float w0 = v0 / wsum, w1 = v1 / wsum;
        int p0 = atomicAdd(&g_cnt[i0], 1);
        int p1 = atomicAdd(&g_cnt[i1], 1);
        g_tok[i0][p0] = t;  g_wt[i0][p0] = w0;
        g_tok[i1][p1] = t;  g_wt[i1][p1] = w1;
        g_tok_e[t][0] = i0; g_tok_p[t][0] = p0;
        g_tok_e[t][1] = i1; g_tok_p[t][1] = p1;
    }
}

// MODE 0: A = gathered tn rows, B = w_gate[e] (HxI)  -> write g_g
// MODE 1: A = gathered tn rows, B = w_up[e]   (HxI)  -> write g_h = silu(g_g)*u
// MODE 2: A = g_h slot rows,    B = w_down[e] (IxH)  -> write g_y = wt * (h @ Wd)
template<int MODE>
__global__ __launch_bounds__(256, 2) void moe_gemm_kernel(const float* __restrict__ W)
{
    constexpr int KD = (MODE == 2) ? IDIM : HDIM;
    constexpr int ND = (MODE == 2) ? HDIM : IDIM;

    int e   = blockIdx.z;
    int cnt = g_cnt[e];
    int m0  = blockIdx.y * BM;
    if (m0 >= cnt) return;
    int n0  = blockIdx.x * BN;
    int off = g_off[e];
    const float* Wb = W + (size_t)e * KD * ND;

    __shared__ float As[BK][BM];
    __shared__ float Bs[BK][BN];

    int tid = threadIdx.x;

    // A-load mapping: 128 rows x 16 cols, thread handles row tid>>1, 8 consecutive cols
    int arow  = tid >> 1;
    int acol0 = (tid & 1) * 8;
    bool avalid = (m0 + arow) < cnt;
    const float* Arow;
    if (MODE == 2) {
        Arow = g_h + (size_t)(off + m0 + arow) * IDIM;
    } else {
        int tok = avalid ? g_tok[e][m0 + arow] : 0;
        Arow = g_tn + (size_t)tok * HDIM;
    }

    // B-load mapping: 16 rows x 128 cols, thread handles row tid>>4, 8 consecutive cols
    int brow  = tid >> 4;
    int bcol0 = (tid & 15) * 8;

    float acc[8][8];
    #pragma unroll
    for (int i = 0; i < 8; i++)
        #pragma unroll
        for (int j = 0; j < 8; j++) acc[i][j] = 0.f;

    int ty = tid >> 4, tx = tid & 15;

    for (int k0 = 0; k0 < KD; k0 += BK) {
        float4 a0, a1;
        if (avalid) {
            a0 = *(const float4*)(Arow + k0 + acol0);
            a1 = *(const float4*)(Arow + k0 + acol0 + 4);
        } else {
            a0 = make_float4(0.f, 0.f, 0.f, 0.f);
            a1 = a0;
        }
        const float* Bp = Wb + (size_t)(k0 + brow) * ND + n0 + bcol0;
        float4 b0 = *(const float4*)Bp;
        float4 b1 = *(const float4*)(Bp + 4);

        As[acol0 + 0][arow] = a0.x;
        As[acol0 + 1][arow] = a0.y;
        As[acol0 + 2][arow] = a0.z;
        As[acol0 + 3][arow] = a0.w;
        As[acol0 + 4][arow] = a1.x;
        As[acol0 + 5][arow] = a1.y;
        As[acol0 + 6][arow] = a1.z;
        As[acol0 + 7][arow] = a1.w;
        *(float4*)&Bs[brow][bcol0]     = b0;
        *(float4*)&Bs[brow][bcol0 + 4] = b1;
        __syncthreads();

        #pragma unroll
        for (int k = 0; k < BK; k++) {
            float ar[8], br[8];
            *(float4*)(ar)     = *(const float4*)&As[k][ty * 8];
            *(float4*)(ar + 4) = *(const float4*)&As[k][ty * 8 + 4];
            *(float4*)(br)     = *(const float4*)&Bs[k][tx * 8];
            *(float4*)(br + 4) = *(const float4*)&Bs[k][tx * 8 + 4];
            #pragma unroll
            for (int i = 0; i < 8; i++)
                #pragma unroll
                for (int j = 0; j < 8; j++)
                    acc[i][j] += ar[i] * br[j];
        }
        __syncthreads();
    }

    // Epilogue
    #pragma unroll
    for (int i = 0; i < 8; i++) {
        int m = m0 + ty * 8 + i;
        if (m >= cnt) continue;
        size_t rb = (size_t)(off + m) * ND + n0 + tx * 8;
        if (MODE == 0) {
            #pragma unroll
            for (int j = 0; j < 8; j += 4) {
                float4 o = make_float4(acc[i][j], acc[i][j+1], acc[i][j+2], acc[i][j+3]);
                *(float4*)&g_g[rb + j] = o;
            }
        } else if (MODE == 1) {
            #pragma unroll
            for (int j = 0; j < 8; j += 4) {
                float4 gg = *(const float4*)&g_g[rb + j];
                float4 o;
                o.x = acc[i][j+0] * (gg.x / (1.f + expf(-gg.x)));
                o.y = acc[i][j+1] * (gg.y / (1.f + expf(-gg.y)));
                o.z = acc[i][j+2] * (gg.z / (1.f + expf(-gg.z)));
                o.w = acc[i][j+3] * (gg.w / (1.f + expf(-gg.w)));
                *(float4*)&g_h[rb + j] = o;
            }
        } else {
            float wt = g_wt[e][m];
            #pragma unroll
            for (int j = 0; j < 8; j += 4) {
                float4 o = make_float4(acc[i][j] * wt, acc[i][j+1] * wt,
                                       acc[i][j+2] * wt, acc[i][j+3] * wt);
                *(float4*)&g_y[rb + j] = o;
            }
        }
    }
}

__global__ __launch_bounds__(256) void combine_kernel(float* __restrict__ out)
{
    int t = blockIdx.x;
    int e0 = g_tok_e[t][0], e1 = g_tok_e[t][1];
    int s0 = g_off[e0] + g_tok_p[t][0];
    int s1 = g_off[e1] + g_tok_p[t][1];
    const float4* y0 = (const float4*)(g_y + (size_t)s0 * HDIM);
    const float4* y1 = (const float4*)(g_y + (size_t)s1 * HDIM);
    float4* o = (float4*)(out + (size_t)t * HDIM);
    for (int h = threadIdx.x; h < HDIM / 4; h += blockDim.x) {
        float4 a = y0[h], b = y1[h];
        o[h] = make_float4(a.x + b.x, a.y + b.y, a.z + b.z, a.w + b.w);
    }
}

extern "C" void kernel_launch(void* const* d_in, const int* in_sizes, int n_in,
                              void* d_out, int out_size)
{
    const float* x        = (const float*)d_in[0];
    const float* norm_w   = (const float*)d_in[1];
    const float* router_w = (const float*)d_in[2];
    const float* w_gate   = (const float*)d_in[3];
    const float* w_up     = (const float*)d_in[4];
    const float* w_down   = (const float*)d_in[5];
    float* out = (float*)d_out;

    zero_cnt_kernel<<<1, 32>>>();
    norm_route_kernel<<<TTOK, 256>>>(x, norm_w, router_w);
    prefix_kernel<<<1, 1>>>();
    moe_gemm_kernel<0><<<dim3(IDIM / BN, TTOK / BM, EEXP), 256>>>(w_gate);
    moe_gemm_kernel<1><<<dim3(IDIM / BN, TTOK / BM, EEXP), 256>>>(w_up);
    moe_gemm_kernel<2><<<dim3(HDIM / BN, TTOK / BM, EEXP), 256>>>(w_down);
    combine_kernel<<<TTOK, 256>>>(out);
}

// round 6
// speedup vs baseline: 2.0451x; 2.0451x over previous
#include <cuda_runtime.h>
#include <cstdint>
#include <math.h>

#define TTOK 2048
#define HDIM 2048
#define IDIM 4096
#define EEXP 8
#define KTOP 2

// ---------------- scratch (device globals; no allocation allowed) ----------
__device__ float g_tn[(size_t)TTOK * HDIM];          // normalized tokens (tf32-rounded)
__device__ int   g_cnt[EEXP];
__device__ int   g_off[EEXP];
__device__ int   g_tok[EEXP][TTOK];
__device__ float g_wt [EEXP][TTOK];
__device__ int   g_tok_e[TTOK][KTOP];
__device__ int   g_tok_p[TTOK][KTOP];
__device__ float g_g[(size_t)TTOK * KTOP * IDIM];    // gate preact (fp32)
__device__ float g_h[(size_t)TTOK * KTOP * IDIM];    // silu(g)*u (tf32-rounded)
__device__ float g_y[(size_t)TTOK * KTOP * HDIM];    // weighted down-proj out

__device__ __forceinline__ uint32_t tf32r(float x) {
    uint32_t u;
    asm("cvt.rna.tf32.f32 %0, %1;" : "=r"(u) : "f"(x));
    return u;
}

__device__ __forceinline__ void mma_tf32(float* c, const uint32_t* a, const uint32_t* b) {
    asm volatile(
        "mma.sync.aligned.m16n8k8.row.col.f32.tf32.tf32.f32 "
        "{%0,%1,%2,%3}, {%4,%5,%6,%7}, {%8,%9}, {%0,%1,%2,%3};"
        : "+f"(c[0]), "+f"(c[1]), "+f"(c[2]), "+f"(c[3])
        : "r"(a[0]), "r"(a[1]), "r"(a[2]), "r"(a[3]), "r"(b[0]), "r"(b[1]));
}

// ---------------- small kernels --------------------------------------------
__global__ void zero_cnt_kernel() { if (threadIdx.x < EEXP) g_cnt[threadIdx.x] = 0; }

__global__ void prefix_kernel() {
    int r = 0;
    for (int e = 0; e < EEXP; e++) { g_off[e] = r; r += g_cnt[e]; }
}

__global__ __launch_bounds__(256) void norm_route_kernel(
    const float* __restrict__ x, const float* __restrict__ norm_w,
    const float* __restrict__ router_w)
{
    int t = blockIdx.x, tid = threadIdx.x;
    __shared__ float s_tn[HDIM];
    __shared__ float s_red[8];
    __shared__ float s_logit[EEXP];

    const float* xr = x + (size_t)t * HDIM;
    float v[8]; float ss = 0.f;
    #pragma unroll
    for (int i = 0; i < 8; i++) { float xv = xr[tid + i * 256]; v[i] = xv; ss += xv * xv; }
    #pragma unroll
    for (int o = 16; o; o >>= 1) ss += __shfl_xor_sync(0xffffffffu, ss, o);
    if ((tid & 31) == 0) s_red[tid >> 5] = ss;
    __syncthreads();
    if (tid < 8) {
        float r = s_red[tid];
        #pragma unroll
        for (int o = 4; o; o >>= 1) r += __shfl_xor_sync(0xffu, r, o);
        if (tid == 0) s_red[0] = r;
    }
    __syncthreads();
    float inv = rsqrtf(s_red[0] * (1.0f / HDIM) + 1e-6f);
    #pragma unroll
    for (int i = 0; i < 8; i++) {
        int h = tid + i * 256;
        float tnv = v[i] * inv * norm_w[h];
        s_tn[h] = tnv;
        // pre-round A operand: HW tf32 read truncates; rna here makes it exact
        g_tn[(size_t)t * HDIM + h] = __uint_as_float(tf32r(tnv));
    }
    __syncthreads();

    int e = tid >> 5, lane = tid & 31;
    float lg = 0.f;
    for (int h = lane; h < HDIM; h += 32) lg += s_tn[h] * router_w[h * EEXP + e];
    #pragma unroll
    for (int o = 16; o; o >>= 1) lg += __shfl_xor_sync(0xffffffffu, lg, o);
    if (lane == 0) s_logit[e] = lg;
    __syncthreads();

    if (tid == 0) {
        float mx = -1e30f;
        #pragma unroll
        for (int i = 0; i < EEXP; i++) mx = fmaxf(mx, s_logit[i]);
        float p[EEXP];
        #pragma unroll
        for (int i = 0; i < EEXP; i++) p[i] = expf(s_logit[i] - mx);
        int i0 = 0;
        #pragma unroll
        for (int i = 1; i < EEXP; i++) if (p[i] > p[i0]) i0 = i;
        int i1 = (i0 == 0) ? 1 : 0;
        #pragma unroll
        for (int i = 0; i < EEXP; i++) { if (i != i0 && p[i] > p[i1]) i1 = i; }
        float v0 = p[i0], v1 = p[i1], wsum = v0 + v1;
        int p0 = atomicAdd(&g_cnt[i0], 1);
        int p1 = atomicAdd(&g_cnt[i1], 1);
        g_tok[i0][p0] = t;  g_wt[i0][p0] = v0 / wsum;
        g_tok[i1][p1] = t;  g_wt[i1][p1] = v1 / wsum;
        g_tok_e[t][0] = i0; g_tok_p[t][0] = p0;
        g_tok_e[t][1] = i1; g_tok_p[t][1] = p1;
    }
}

// ---------------- tf32 mma.sync grouped GEMM --------------------------------
// MODE 0: A=g_tn(gather)  B=w_gate[e] [H,I]  -> g_g            (K=H, N=I)
// MODE 1: A=g_tn(gather)  B=w_up[e]   [H,I]  -> g_h=silu(g)*u  (K=H, N=I)
// MODE 2: A=g_h rows      B=w_down[e] [I,H]  -> g_y=wt*(h@Wd)  (K=I, N=H)
#define BM  128
#define BN  128
#define BK  32
#define APAD 36    // 36 % 32 == 4 -> bank(4m+k) unique across quad: conflict-free
#define BPAD 136   // 136 % 32 == 8 -> bank(8k+n) unique across quad: conflict-free

template<int MODE>
__global__ __launch_bounds__(256, 2) void moe_mma_gemm(const float* __restrict__ W)
{
    constexpr int KD = (MODE == 2) ? IDIM : HDIM;
    constexpr int ND = (MODE == 2) ? HDIM : IDIM;

    int e   = blockIdx.z;
    int cnt = g_cnt[e];
    int m0  = blockIdx.y * BM;
    if (m0 >= cnt) return;
    int n0  = blockIdx.x * BN;
    int off = g_off[e];
    const float* Wb = W + (size_t)e * KD * ND;

    __shared__ float sA[BM * APAD];          // A row-major [m][k], pad 36
    __shared__ float sB[BK * BPAD];          // B row-major [k][n], pad 136
    __shared__ const float* s_aptr[BM];

    int tid  = threadIdx.x;
    int wid  = tid >> 5, lane = tid & 31;
    int mW   = (wid >> 2) * 64;              // warp m-offset (2 warps in M)
    int nW   = (wid & 3) * 32;               // warp n-offset (4 warps in N)

    {
        int m = m0 + (tid >> 1);             // 2 threads per row; thread 0 of pair writes
        if ((tid & 1) == 0) {
            const float* p = nullptr;
            if (m < cnt) {
                if (MODE == 2) p = g_h + (size_t)(off + m) * IDIM;
                else           p = g_tn + (size_t)g_tok[e][m] * HDIM;
            }
            s_aptr[tid >> 1] = p;
        }
    }
    __syncthreads();                         // s_aptr visible to ALL before staging

    float acc[4][4][4];
    #pragma unroll
    for (int i = 0; i < 4; i++)
        #pragma unroll
        for (int j = 0; j < 4; j++)
            #pragma unroll
            for (int k = 0; k < 4; k++) acc[i][j][k] = 0.f;

    const uint32_t* sAu = (const uint32_t*)sA;
    const uint32_t* sBu = (const uint32_t*)sB;

    // B prefetch thread mapping (fixed across chunks)
    int pk = tid >> 5;            // k-row 0..7  (x4 via it*8)
    int pn = tid & 31;            // float4 col 0..31

    // ---- prefetch B chunk 0 into registers (DRAM-latency stream) ----
    uint4 rb[4];
    #pragma unroll
    for (int it = 0; it < 4; it++) {
        float4 v = *(const float4*)(Wb + (size_t)(pk + it * 8) * ND + n0 + pn * 4);
        rb[it].x = tf32r(v.x); rb[it].y = tf32r(v.y);
        rb[it].z = tf32r(v.z); rb[it].w = tf32r(v.w);
    }

    for (int k0 = 0; k0 < KD; k0 += BK) {
        if (k0) __syncthreads();             // previous compute done before restage

        // stage A direct (L2-resident stream): 128 rows x 8 float4
        #pragma unroll
        for (int it = 0; it < 4; it++) {
            int f = tid + it * 256;
            int row = f >> 3, c4 = f & 7;
            const float* p = s_aptr[row];
            float4 v = p ? *(const float4*)(p + k0 + c4 * 4)
                         : make_float4(0.f, 0.f, 0.f, 0.f);
            *(float4*)&sA[row * APAD + c4 * 4] = v;
        }
        // stage B from prefetched registers
        #pragma unroll
        for (int it = 0; it < 4; it++)
            *(uint4*)&sB[(pk + it * 8) * BPAD + pn * 4] = rb[it];
        __syncthreads();

        // ---- prefetch next B chunk while computing this one ----
        if (k0 + BK < KD) {
            const float* Bp = Wb + (size_t)(k0 + BK + pk) * ND + n0 + pn * 4;
            #pragma unroll
            for (int it = 0; it < 4; it++) {
                float4 v = *(const float4*)(Bp + (size_t)(it * 8) * ND);
                rb[it].x = tf32r(v.x); rb[it].y = tf32r(v.y);
                rb[it].z = tf32r(v.z); rb[it].w = tf32r(v.w);
            }
        }

        #pragma unroll
        for (int ks = 0; ks < 4; ks++) {
            uint32_t af[4][4], bf[4][2];
            int ak = ks * 8 + (lane & 3);
            int ar = mW + (lane >> 2);
            #pragma unroll
            for (int mt = 0; mt < 4; mt++) {
                int r = ar + mt * 16;
                af[mt][0] = sAu[(size_t)r * APAD + ak];
                af[mt][1] = sAu[(size_t)(r + 8) * APAD + ak];
                af[mt][2] = sAu[(size_t)r * APAD + ak + 4];
                af[mt][3] = sAu[(size_t)(r + 8) * APAD + ak + 4];
            }
            int bk = ks * 8 + (lane & 3);
            int bn = nW + (lane >> 2);
            #pragma unroll
            for (int nt = 0; nt < 4; nt++) {
                bf[nt][0] = sBu[(size_t)bk * BPAD + bn + nt * 8];
                bf[nt][1] = sBu[(size_t)(bk + 4) * BPAD + bn + nt * 8];
            }
            #pragma unroll
            for (int mt = 0; mt < 4; mt++)
                #pragma unroll
                for (int nt = 0; nt < 4; nt++)
                    mma_tf32(acc[mt][nt], af[mt], bf[nt]);
        }
    }

    // ---- epilogue ----
    int rr = lane >> 2, cc = (lane & 3) * 2;
    #pragma unroll
    for (int mt = 0; mt < 4; mt++) {
        #pragma unroll
        for (int half = 0; half < 2; half++) {
            int m = m0 + mW + mt * 16 + rr + half * 8;
            if (m >= cnt) continue;
            size_t rowbase = (size_t)(off + m) * ND;
            float wt = (MODE == 2) ? g_wt[e][m] : 0.f;
            #pragma unroll
            for (int nt = 0; nt < 4; nt++) {
                size_t idx = rowbase + n0 + nW + nt * 8 + cc;
                float v0 = acc[mt][nt][half * 2 + 0];
                float v1 = acc[mt][nt][half * 2 + 1];
                if (MODE == 0) {
                    *(float2*)&g_g[idx] = make_float2(v0, v1);
                } else if (MODE == 1) {
                    float2 gg = *(const float2*)&g_g[idx];
                    float h0 = v0 * (gg.x / (1.f + expf(-gg.x)));
                    float h1 = v1 * (gg.y / (1.f + expf(-gg.y)));
                    uint2 hh;
                    hh.x = tf32r(h0); hh.y = tf32r(h1);
                    *(uint2*)&g_h[idx] = hh;
                } else {
                    *(float2*)&g_y[idx] = make_float2(v0 * wt, v1 * wt);
                }
            }
        }
    }
}

__global__ __launch_bounds__(256) void combine_kernel(float* __restrict__ out)
{
    int t = blockIdx.x;
    int e0 = g_tok_e[t][0], e1 = g_tok_e[t][1];
    int s0 = g_off[e0] + g_tok_p[t][0];
    int s1 = g_off[e1] + g_tok_p[t][1];
    const float4* y0 = (const float4*)(g_y + (size_t)s0 * HDIM);
    const float4* y1 = (const float4*)(g_y + (size_t)s1 * HDIM);
    float4* o = (float4*)(out + (size_t)t * HDIM);
    for (int h = threadIdx.x; h < HDIM / 4; h += blockDim.x) {
        float4 a = y0[h], b = y1[h];
        o[h] = make_float4(a.x + b.x, a.y + b.y, a.z + b.z, a.w + b.w);
    }
}

extern "C" void kernel_launch(void* const* d_in, const int* in_sizes, int n_in,
                              void* d_out, int out_size)
{
    const float* x        = (const float*)d_in[0];
    const float* norm_w   = (const float*)d_in[1];
    const float* router_w = (const float*)d_in[2];
    const float* w_gate   = (const float*)d_in[3];
    const float* w_up     = (const float*)d_in[4];
    const float* w_down   = (const float*)d_in[5];
    float* out = (float*)d_out;

    zero_cnt_kernel<<<1, 32>>>();
    norm_route_kernel<<<TTOK, 256>>>(x, norm_w, router_w);
    prefix_kernel<<<1, 1>>>();
    moe_mma_gemm<0><<<dim3(IDIM / BN, TTOK / BM, EEXP), 256>>>(w_gate);
    moe_mma_gemm<1><<<dim3(IDIM / BN, TTOK / BM, EEXP), 256>>>(w_up);
    moe_mma_gemm<2><<<dim3(HDIM / BN, TTOK / BM, EEXP), 256>>>(w_down);
    combine_kernel<<<TTOK, 256>>>(out);
}

// round 7
// speedup vs baseline: 2.9797x; 1.4570x over previous
#include <cuda_runtime.h>
#include <cstdint>
#include <math.h>

#define TTOK 2048
#define HDIM 2048
#define IDIM 4096
#define EEXP 8
#define KTOP 2

// ---------------- scratch (device globals; no allocation allowed) ----------
__device__ float g_tn[(size_t)TTOK * HDIM];          // normalized tokens (tf32-rounded)
__device__ int   g_cnt[EEXP];
__device__ int   g_off[EEXP];
__device__ int   g_tok[EEXP][TTOK];
__device__ float g_wt [EEXP][TTOK];
__device__ int   g_tok_e[TTOK][KTOP];
__device__ int   g_tok_p[TTOK][KTOP];
__device__ float g_g[(size_t)TTOK * KTOP * IDIM];    // gate preact (fp32)
__device__ float g_h[(size_t)TTOK * KTOP * IDIM];    // silu(g)*u (tf32-rounded)
__device__ float g_y[(size_t)TTOK * KTOP * HDIM];    // weighted down-proj out

__device__ __forceinline__ uint32_t tf32r(float x) {
    uint32_t u;
    asm("cvt.rna.tf32.f32 %0, %1;" : "=r"(u) : "f"(x));
    return u;
}

__device__ __forceinline__ void mma_tf32(float* c, const uint32_t* a, const uint32_t* b) {
    asm volatile(
        "mma.sync.aligned.m16n8k8.row.col.f32.tf32.tf32.f32 "
        "{%0,%1,%2,%3}, {%4,%5,%6,%7}, {%8,%9}, {%0,%1,%2,%3};"
        : "+f"(c[0]), "+f"(c[1]), "+f"(c[2]), "+f"(c[3])
        : "r"(a[0]), "r"(a[1]), "r"(a[2]), "r"(a[3]), "r"(b[0]), "r"(b[1]));
}

__device__ __forceinline__ uint32_t smem_u32(const void* p) {
    uint32_t a;
    asm("{ .reg .u64 t; cvta.to.shared.u64 t, %1; cvt.u32.u64 %0, t; }" : "=r"(a) : "l"(p));
    return a;
}
__device__ __forceinline__ void cp_async16(uint32_t dst, const void* src) {
    asm volatile("cp.async.cg.shared.global [%0], [%1], 16;" :: "r"(dst), "l"(src));
}
#define CP_COMMIT() asm volatile("cp.async.commit_group;" ::: "memory")
#define CP_WAIT0()  asm volatile("cp.async.wait_group 0;"  ::: "memory")

// ---------------- small kernels --------------------------------------------
__global__ void zero_cnt_kernel() { if (threadIdx.x < EEXP) g_cnt[threadIdx.x] = 0; }

__global__ void prefix_kernel() {
    int r = 0;
    for (int e = 0; e < EEXP; e++) { g_off[e] = r; r += g_cnt[e]; }
}

__global__ __launch_bounds__(256) void norm_route_kernel(
    const float* __restrict__ x, const float* __restrict__ norm_w,
    const float* __restrict__ router_w)
{
    int t = blockIdx.x, tid = threadIdx.x;
    __shared__ float s_tn[HDIM];
    __shared__ float s_red[8];
    __shared__ float s_logit[EEXP];

    const float* xr = x + (size_t)t * HDIM;
    float v[8]; float ss = 0.f;
    #pragma unroll
    for (int i = 0; i < 8; i++) { float xv = xr[tid + i * 256]; v[i] = xv; ss += xv * xv; }
    #pragma unroll
    for (int o = 16; o; o >>= 1) ss += __shfl_xor_sync(0xffffffffu, ss, o);
    if ((tid & 31) == 0) s_red[tid >> 5] = ss;
    __syncthreads();
    if (tid < 8) {
        float r = s_red[tid];
        #pragma unroll
        for (int o = 4; o; o >>= 1) r += __shfl_xor_sync(0xffu, r, o);
        if (tid == 0) s_red[0] = r;
    }
    __syncthreads();
    float inv = rsqrtf(s_red[0] * (1.0f / HDIM) + 1e-6f);
    #pragma unroll
    for (int i = 0; i < 8; i++) {
        int h = tid + i * 256;
        float tnv = v[i] * inv * norm_w[h];
        s_tn[h] = tnv;
        // pre-round A operand: HW tf32 read truncates; rna here makes it exact
        g_tn[(size_t)t * HDIM + h] = __uint_as_float(tf32r(tnv));
    }
    __syncthreads();

    int e = tid >> 5, lane = tid & 31;
    float lg = 0.f;
    for (int h = lane; h < HDIM; h += 32) lg += s_tn[h] * router_w[h * EEXP + e];
    #pragma unroll
    for (int o = 16; o; o >>= 1) lg += __shfl_xor_sync(0xffffffffu, lg, o);
    if (lane == 0) s_logit[e] = lg;
    __syncthreads();

    if (tid == 0) {
        float mx = -1e30f;
        #pragma unroll
        for (int i = 0; i < EEXP; i++) mx = fmaxf(mx, s_logit[i]);
        float p[EEXP];
        #pragma unroll
        for (int i = 0; i < EEXP; i++) p[i] = expf(s_logit[i] - mx);
        int i0 = 0;
        #pragma unroll
        for (int i = 1; i < EEXP; i++) if (p[i] > p[i0]) i0 = i;
        int i1 = (i0 == 0) ? 1 : 0;
        #pragma unroll
        for (int i = 0; i < EEXP; i++) { if (i != i0 && p[i] > p[i1]) i1 = i; }
        float v0 = p[i0], v1 = p[i1], wsum = v0 + v1;
        int p0 = atomicAdd(&g_cnt[i0], 1);
        int p1 = atomicAdd(&g_cnt[i1], 1);
        g_tok[i0][p0] = t;  g_wt[i0][p0] = v0 / wsum;
        g_tok[i1][p1] = t;  g_wt[i1][p1] = v1 / wsum;
        g_tok_e[t][0] = i0; g_tok_p[t][0] = p0;
        g_tok_e[t][1] = i1; g_tok_p[t][1] = p1;
    }
}

// ---------------- tf32 mma.sync grouped GEMM, double-buffered ---------------
// MODE 0: A=g_tn(gather)  B=w_gate[e] [H,I]  -> g_g            (K=H, N=I)
// MODE 1: A=g_tn(gather)  B=w_up[e]   [H,I]  -> g_h=silu(g)*u  (K=H, N=I)
// MODE 2: A=g_h rows      B=w_down[e] [I,H]  -> g_y=wt*(h@Wd)  (K=I, N=H)
#define BM  128
#define BN  128
#define BK  32
#define APAD 36    // 36 % 32 == 4 -> bank(4m+k) unique across quad: conflict-free
#define BPAD 136   // 136 % 32 == 8 -> bank(8k+n) unique across quad: conflict-free

#define SZ_A (BM * APAD * 4)     // 18432 B
#define SZ_B (BK * BPAD * 4)     // 17408 B
#define SMEM_DYN (2 * SZ_A + 2 * SZ_B)   // 71680 B

template<int MODE>
__global__ __launch_bounds__(256, 2) void moe_mma_gemm(const float* __restrict__ W)
{
    constexpr int KD = (MODE == 2) ? IDIM : HDIM;
    constexpr int ND = (MODE == 2) ? HDIM : IDIM;
    constexpr int NC = KD / BK;

    int e   = blockIdx.z;
    int cnt = g_cnt[e];
    int m0  = blockIdx.y * BM;
    if (m0 >= cnt) return;
    int n0  = blockIdx.x * BN;
    int off = g_off[e];
    const float* Wb = W + (size_t)e * KD * ND;

    extern __shared__ float dsm[];
    float* sA[2] = { dsm,                dsm + BM * APAD };
    float* sB[2] = { dsm + 2 * BM * APAD, dsm + 2 * BM * APAD + BK * BPAD };
    uint32_t sAu32[2] = { smem_u32(sA[0]), smem_u32(sA[1]) };

    __shared__ const float* s_aptr[BM];

    int tid  = threadIdx.x;
    int wid  = tid >> 5, lane = tid & 31;
    int mW   = (wid >> 2) * 64;              // warp m-offset (2 warps in M)
    int nW   = (wid & 3) * 32;               // warp n-offset (4 warps in N)

    {
        int m = m0 + (tid >> 1);
        if ((tid & 1) == 0) {
            const float* p;
            if (MODE == 2) p = g_h + (size_t)(off + ((m < cnt) ? m : 0)) * IDIM;
            else           p = g_tn + (size_t)g_tok[e][(m < cnt) ? m : 0] * HDIM;
            s_aptr[tid >> 1] = p;   // invalid rows alias row 0; never stored
        }
    }
    __syncthreads();

    float acc[4][4][4];
    #pragma unroll
    for (int i = 0; i < 4; i++)
        #pragma unroll
        for (int j = 0; j < 4; j++)
            #pragma unroll
            for (int k = 0; k < 4; k++) acc[i][j][k] = 0.f;

    // thread mappings for staging (fixed across chunks)
    int arow = tid >> 1, ac4 = (tid & 1) * 4;        // A: 2 thr/row? -> see loop below
    (void)arow; (void)ac4;
    int pk = tid >> 5;            // B k-row 0..7  (x4 via it*8)
    int pn = tid & 31;            // B float4 col 0..31

    // ---- A cp.async issue (chunk k0 -> buffer buf) ----
    auto issueA = [&](int buf, int k0) {
        #pragma unroll
        for (int it = 0; it < 4; it++) {
            int f = tid + it * 256;
            int row = f >> 3, c4 = f & 7;
            cp_async16(sAu32[buf] + (uint32_t)(row * APAD + c4 * 4) * 4,
                       s_aptr[row] + k0 + c4 * 4);
        }
        CP_COMMIT();
    };
    // ---- B LDG into registers ----
    uint4 rb[4];
    auto ldgB = [&](int k0) {
        const float* Bp = Wb + (size_t)(k0 + pk) * ND + n0 + pn * 4;
        #pragma unroll
        for (int it = 0; it < 4; it++) {
            float4 v = *(const float4*)(Bp + (size_t)(it * 8) * ND);
            rb[it].x = tf32r(v.x); rb[it].y = tf32r(v.y);
            rb[it].z = tf32r(v.z); rb[it].w = tf32r(v.w);
        }
    };
    auto stsB = [&](int buf) {
        #pragma unroll
        for (int it = 0; it < 4; it++)
            *(uint4*)&sB[buf][(pk + it * 8) * BPAD + pn * 4] = rb[it];
    };

    const uint32_t* sAc;
    const uint32_t* sBc;

    // ---- prologue: fill buffer 0 ----
    issueA(0, 0);
    ldgB(0);
    CP_WAIT0();
    stsB(0);
    __syncthreads();

    for (int c = 0; c < NC; c++) {
        int b = c & 1;
        if (c + 1 < NC) {
            issueA(b ^ 1, (c + 1) * BK);     // async into alt buffer
            ldgB((c + 1) * BK);              // DRAM latency covered by compute
        }

        sAc = (const uint32_t*)sA[b];
        sBc = (const uint32_t*)sB[b];
        #pragma unroll
        for (int ks = 0; ks < 4; ks++) {
            uint32_t af[4][4], bf[4][2];
            int ak = ks * 8 + (lane & 3);
            int ar = mW + (lane >> 2);
            #pragma unroll
            for (int mt = 0; mt < 4; mt++) {
                int r = ar + mt * 16;
                af[mt][0] = sAc[(size_t)r * APAD + ak];
                af[mt][1] = sAc[(size_t)(r + 8) * APAD + ak];
                af[mt][2] = sAc[(size_t)r * APAD + ak + 4];
                af[mt][3] = sAc[(size_t)(r + 8) * APAD + ak + 4];
            }
            int bk = ks * 8 + (lane & 3);
            int bn = nW + (lane >> 2);
            #pragma unroll
            for (int nt = 0; nt < 4; nt++) {
                bf[nt][0] = sBc[(size_t)bk * BPAD + bn + nt * 8];
                bf[nt][1] = sBc[(size_t)(bk + 4) * BPAD + bn + nt * 8];
            }
            #pragma unroll
            for (int mt = 0; mt < 4; mt++)
                #pragma unroll
                for (int nt = 0; nt < 4; nt++)
                    mma_tf32(acc[mt][nt], af[mt], bf[nt]);
        }

        if (c + 1 < NC) {
            stsB(b ^ 1);       // alt buffer; current compute already done
            CP_WAIT0();
        }
        __syncthreads();
    }

    // ---- epilogue ----
    int rr = lane >> 2, cc = (lane & 3) * 2;
    #pragma unroll
    for (int mt = 0; mt < 4; mt++) {
        #pragma unroll
        for (int half = 0; half < 2; half++) {
            int m = m0 + mW + mt * 16 + rr + half * 8;
            if (m >= cnt) continue;
            size_t rowbase = (size_t)(off + m) * ND;
            float wt = (MODE == 2) ? g_wt[e][m] : 0.f;
            #pragma unroll
            for (int nt = 0; nt < 4; nt++) {
                size_t idx = rowbase + n0 + nW + nt * 8 + cc;
                float v0 = acc[mt][nt][half * 2 + 0];
                float v1 = acc[mt][nt][half * 2 + 1];
                if (MODE == 0) {
                    *(float2*)&g_g[idx] = make_float2(v0, v1);
                } else if (MODE == 1) {
                    float2 gg = *(const float2*)&g_g[idx];
                    float h0 = v0 * (gg.x / (1.f + expf(-gg.x)));
                    float h1 = v1 * (gg.y / (1.f + expf(-gg.y)));
                    uint2 hh;
                    hh.x = tf32r(h0); hh.y = tf32r(h1);
                    *(uint2*)&g_h[idx] = hh;
                } else {
                    *(float2*)&g_y[idx] = make_float2(v0 * wt, v1 * wt);
                }
            }
        }
    }
}

__global__ __launch_bounds__(256) void combine_kernel(float* __restrict__ out)
{
    int t = blockIdx.x;
    int e0 = g_tok_e[t][0], e1 = g_tok_e[t][1];
    int s0 = g_off[e0] + g_tok_p[t][0];
    int s1 = g_off[e1] + g_tok_p[t][1];
    const float4* y0 = (const float4*)(g_y + (size_t)s0 * HDIM);
    const float4* y1 = (const float4*)(g_y + (size_t)s1 * HDIM);
    float4* o = (float4*)(out + (size_t)t * HDIM);
    for (int h = threadIdx.x; h < HDIM / 4; h += blockDim.x) {
        float4 a = y0[h], b = y1[h];
        o[h] = make_float4(a.x + b.x, a.y + b.y, a.z + b.z, a.w + b.w);
    }
}

extern "C" void kernel_launch(void* const* d_in, const int* in_sizes, int n_in,
                              void* d_out, int out_size)
{
    const float* x        = (const float*)d_in[0];
    const float* norm_w   = (const float*)d_in[1];
    const float* router_w = (const float*)d_in[2];
    const float* w_gate   = (const float*)d_in[3];
    const float* w_up     = (const float*)d_in[4];
    const float* w_down   = (const float*)d_in[5];
    float* out = (float*)d_out;

    cudaFuncSetAttribute(moe_mma_gemm<0>, cudaFuncAttributeMaxDynamicSharedMemorySize, SMEM_DYN);
    cudaFuncSetAttribute(moe_mma_gemm<1>, cudaFuncAttributeMaxDynamicSharedMemorySize, SMEM_DYN);
    cudaFuncSetAttribute(moe_mma_gemm<2>, cudaFuncAttributeMaxDynamicSharedMemorySize, SMEM_DYN);

    zero_cnt_kernel<<<1, 32>>>();
    norm_route_kernel<<<TTOK, 256>>>(x, norm_w, router_w);
    prefix_kernel<<<1, 1>>>();
    moe_mma_gemm<0><<<dim3(IDIM / BN, TTOK / BM, EEXP), 256, SMEM_DYN>>>(w_gate);
    moe_mma_gemm<1><<<dim3(IDIM / BN, TTOK / BM, EEXP), 256, SMEM_DYN>>>(w_up);
    moe_mma_gemm<2><<<dim3(HDIM / BN, TTOK / BM, EEXP), 256, SMEM_DYN>>>(w_down);
    combine_kernel<<<TTOK, 256>>>(out);
}

// round 10
// speedup vs baseline: 3.7785x; 1.2681x over previous
#include <cuda_runtime.h>
#include <cstdint>
#include <math.h>

#define TTOK 2048
#define HDIM 2048
#define IDIM 4096
#define EEXP 8
#define KTOP 2

// ---------------- scratch (device globals; no allocation allowed) ----------
__device__ float g_tn[(size_t)TTOK * HDIM];          // normalized tokens (tf32-rounded)
__device__ int   g_cnt[EEXP];
__device__ int   g_off[EEXP];
__device__ int   g_tok[EEXP][TTOK];
__device__ float g_wt [EEXP][TTOK];
__device__ int   g_tok_e[TTOK][KTOP];
__device__ int   g_tok_p[TTOK][KTOP];
__device__ float g_g[(size_t)TTOK * KTOP * IDIM];    // gate preact (fp32)
__device__ float g_h[(size_t)TTOK * KTOP * IDIM];    // silu(g)*u (tf32-rounded)
__device__ float g_y[(size_t)TTOK * KTOP * HDIM];    // weighted down-proj out

__device__ __forceinline__ uint32_t tf32r(float x) {
    uint32_t u;
    asm("cvt.rna.tf32.f32 %0, %1;" : "=r"(u) : "f"(x));
    return u;
}

__device__ __forceinline__ void mma_tf32(float* c, const uint32_t* a, const uint32_t* b) {
    asm volatile(
        "mma.sync.aligned.m16n8k8.row.col.f32.tf32.tf32.f32 "
        "{%0,%1,%2,%3}, {%4,%5,%6,%7}, {%8,%9}, {%0,%1,%2,%3};"
        : "+f"(c[0]), "+f"(c[1]), "+f"(c[2]), "+f"(c[3])
        : "r"(a[0]), "r"(a[1]), "r"(a[2]), "r"(a[3]), "r"(b[0]), "r"(b[1]));
}

__device__ __forceinline__ uint32_t smem_u32(const void* p) {
    uint32_t a;
    asm("{ .reg .u64 t; cvta.to.shared.u64 t, %1; cvt.u32.u64 %0, t; }" : "=r"(a) : "l"(p));
    return a;
}
__device__ __forceinline__ void cp_async16(uint32_t dst, const void* src) {
    asm volatile("cp.async.cg.shared.global [%0], [%1], 16;" :: "r"(dst), "l"(src));
}
#define CP_COMMIT() asm volatile("cp.async.commit_group;" ::: "memory")
#define CP_WAIT1()  asm volatile("cp.async.wait_group 1;"  ::: "memory")
#define CP_WAIT0()  asm volatile("cp.async.wait_group 0;"  ::: "memory")

// ---------------- small kernels --------------------------------------------
__global__ void zero_cnt_kernel() { if (threadIdx.x < EEXP) g_cnt[threadIdx.x] = 0; }

__global__ void prefix_kernel() {
    int r = 0;
    for (int e = 0; e < EEXP; e++) { g_off[e] = r; r += g_cnt[e]; }
}

__global__ __launch_bounds__(256) void norm_route_kernel(
    const float* __restrict__ x, const float* __restrict__ norm_w,
    const float* __restrict__ router_w)
{
    int t = blockIdx.x, tid = threadIdx.x;
    __shared__ float s_tn[HDIM];
    __shared__ float s_red[8];
    __shared__ float s_logit[EEXP];

    const float* xr = x + (size_t)t * HDIM;
    float v[8]; float ss = 0.f;
    #pragma unroll
    for (int i = 0; i < 8; i++) { float xv = xr[tid + i * 256]; v[i] = xv; ss += xv * xv; }
    #pragma unroll
    for (int o = 16; o; o >>= 1) ss += __shfl_xor_sync(0xffffffffu, ss, o);
    if ((tid & 31) == 0) s_red[tid >> 5] = ss;
    __syncthreads();
    if (tid < 8) {
        float r = s_red[tid];
        #pragma unroll
        for (int o = 4; o; o >>= 1) r += __shfl_xor_sync(0xffu, r, o);
        if (tid == 0) s_red[0] = r;
    }
    __syncthreads();
    float inv = rsqrtf(s_red[0] * (1.0f / HDIM) + 1e-6f);
    #pragma unroll
    for (int i = 0; i < 8; i++) {
        int h = tid + i * 256;
        float tnv = v[i] * inv * norm_w[h];
        s_tn[h] = tnv;
        // pre-round A operand: HW tf32 read truncates; rna here makes it exact
        g_tn[(size_t)t * HDIM + h] = __uint_as_float(tf32r(tnv));
    }
    __syncthreads();

    int e = tid >> 5, lane = tid & 31;
    float lg = 0.f;
    for (int h = lane; h < HDIM; h += 32) lg += s_tn[h] * router_w[h * EEXP + e];
    #pragma unroll
    for (int o = 16; o; o >>= 1) lg += __shfl_xor_sync(0xffffffffu, lg, o);
    if (lane == 0) s_logit[e] = lg;
    __syncthreads();

    if (tid == 0) {
        float mx = -1e30f;
        #pragma unroll
        for (int i = 0; i < EEXP; i++) mx = fmaxf(mx, s_logit[i]);
        float p[EEXP];
        #pragma unroll
        for (int i = 0; i < EEXP; i++) p[i] = expf(s_logit[i] - mx);
        int i0 = 0;
        #pragma unroll
        for (int i = 1; i < EEXP; i++) if (p[i] > p[i0]) i0 = i;
        int i1 = (i0 == 0) ? 1 : 0;
        #pragma unroll
        for (int i = 0; i < EEXP; i++) { if (i != i0 && p[i] > p[i1]) i1 = i; }
        float v0 = p[i0], v1 = p[i1], wsum = v0 + v1;
        int p0 = atomicAdd(&g_cnt[i0], 1);
        int p1 = atomicAdd(&g_cnt[i1], 1);
        g_tok[i0][p0] = t;  g_wt[i0][p0] = v0 / wsum;
        g_tok[i1][p1] = t;  g_wt[i1][p1] = v1 / wsum;
        g_tok_e[t][0] = i0; g_tok_p[t][0] = p0;
        g_tok_e[t][1] = i1; g_tok_p[t][1] = p1;
    }
}

// ---------------- tf32 mma.sync grouped GEMM, 3-stage cp.async --------------
// MODE 0: A=g_tn(gather)  B=w_gate[e] [H,I]  -> g_g            (K=H, N=I)
// MODE 1: A=g_tn(gather)  B=w_up[e]   [H,I]  -> g_h=silu(g)*u  (K=H, N=I)
// MODE 2: A=g_h rows      B=w_down[e] [I,H]  -> g_y=wt*(h@Wd)  (K=I, N=H)
#define BM  128
#define BN  128
#define BK  32
#define APAD 36    // 36 % 32 == 4 -> bank(4m+k) unique across quad: conflict-free
#define BPAD 136   // 136 % 32 == 8 -> bank(8k+n) unique across quad: conflict-free
#define STAGES 3

#define SZ_AW (BM * APAD)        // words per A stage
#define SZ_BW (BK * BPAD)        // words per B stage
#define SMEM_DYN ((STAGES * SZ_AW + STAGES * SZ_BW) * 4)   // 107520 B

template<int MODE>
__global__ __launch_bounds__(256, 2) void moe_mma_gemm(const float* __restrict__ W)
{
    constexpr int KD = (MODE == 2) ? IDIM : HDIM;
    constexpr int ND = (MODE == 2) ? HDIM : IDIM;
    constexpr int NC = KD / BK;

    int e   = blockIdx.z;
    int cnt = g_cnt[e];
    int m0  = blockIdx.y * BM;
    if (m0 >= cnt) return;
    int n0  = blockIdx.x * BN;
    int off = g_off[e];
    const float* Wb = W + (size_t)e * KD * ND;

    extern __shared__ float dsm[];
    float*   dB   = dsm + STAGES * SZ_AW;
    uint32_t sAu0 = smem_u32(dsm);
    uint32_t sBu0 = smem_u32(dB);

    __shared__ const float* s_aptr[BM];

    int tid  = threadIdx.x;
    int wid  = tid >> 5, lane = tid & 31;
    int mW   = (wid >> 2) * 64;              // warp m-offset (2 warps in M)
    int nW   = (wid & 3) * 32;               // warp n-offset (4 warps in N)

    {
        int m = m0 + (tid >> 1);
        if ((tid & 1) == 0) {
            const float* p;
            if (MODE == 2) p = g_h + (size_t)(off + ((m < cnt) ? m : 0)) * IDIM;
            else           p = g_tn + (size_t)g_tok[e][(m < cnt) ? m : 0] * HDIM;
            s_aptr[tid >> 1] = p;   // invalid rows alias row 0; never stored
        }
    }
    __syncthreads();

    float acc[4][4][4];
    #pragma unroll
    for (int i = 0; i < 4; i++)
        #pragma unroll
        for (int j = 0; j < 4; j++)
            #pragma unroll
            for (int k = 0; k < 4; k++) acc[i][j][k] = 0.f;

    // ---- stage issue: A (4x cp.async) + B (4x cp.async), one commit group --
    auto issueAB = [&](int stage, int k0) {
        #pragma unroll
        for (int it = 0; it < 4; it++) {
            int f = tid + it * 256;
            int row = f >> 3, c4 = f & 7;
            cp_async16(sAu0 + (uint32_t)(stage * SZ_AW + row * APAD + c4 * 4) * 4,
                       s_aptr[row] + k0 + c4 * 4);
        }
        int bk = tid >> 5, pn = tid & 31;
        #pragma unroll
        for (int it = 0; it < 4; it++) {
            int k = bk + it * 8;
            cp_async16(sBu0 + (uint32_t)(stage * SZ_BW + k * BPAD + pn * 4) * 4,
                       Wb + (size_t)(k0 + k) * ND + n0 + pn * 4);
        }
        CP_COMMIT();
    };

    // ---- prologue: stages 0 and 1 in flight ----
    issueAB(0, 0);
    issueAB(1, BK);

    for (int c = 0; c < NC; c++) {
        // Drain-aware wait: while a younger group is also pending, wait_group 1
        // leaves exactly it in flight. On the FINAL chunk only one group is
        // pending, so wait_group 1 would not wait at all -> must wait_group 0.
        if (c + 1 < NC) CP_WAIT1(); else CP_WAIT0();
        __syncthreads();
        if (c + 2 < NC) issueAB((c + 2) % STAGES, (c + 2) * BK);

        const uint32_t* sAc = (const uint32_t*)(dsm + (c % STAGES) * SZ_AW);
        const float*    sBc = dB + (c % STAGES) * SZ_BW;

        #pragma unroll
        for (int ks = 0; ks < 4; ks++) {
            uint32_t af[4][4], bf[4][2];
            int ak = ks * 8 + (lane & 3);
            int ar = mW + (lane >> 2);
            #pragma unroll
            for (int mt = 0; mt < 4; mt++) {
                int r = ar + mt * 16;
                af[mt][0] = sAc[(size_t)r * APAD + ak];
                af[mt][1] = sAc[(size_t)(r + 8) * APAD + ak];
                af[mt][2] = sAc[(size_t)r * APAD + ak + 4];
                af[mt][3] = sAc[(size_t)(r + 8) * APAD + ak + 4];
            }
            int bk = ks * 8 + (lane & 3);
            int bn = nW + (lane >> 2);
            #pragma unroll
            for (int nt = 0; nt < 4; nt++) {
                // round B on the fragment (numerically identical to staging-time rna)
                bf[nt][0] = tf32r(sBc[(size_t)bk * BPAD + bn + nt * 8]);
                bf[nt][1] = tf32r(sBc[(size_t)(bk + 4) * BPAD + bn + nt * 8]);
            }
            #pragma unroll
            for (int mt = 0; mt < 4; mt++)
                #pragma unroll
                for (int nt = 0; nt < 4; nt++)
                    mma_tf32(acc[mt][nt], af[mt], bf[nt]);
        }
    }

    // ---- epilogue ----
    int rr = lane >> 2, cc = (lane & 3) * 2;
    #pragma unroll
    for (int mt = 0; mt < 4; mt++) {
        #pragma unroll
        for (int half = 0; half < 2; half++) {
            int m = m0 + mW + mt * 16 + rr + half * 8;
            if (m >= cnt) continue;
            size_t rowbase = (size_t)(off + m) * ND;
            float wt = (MODE == 2) ? g_wt[e][m] : 0.f;
            #pragma unroll
            for (int nt = 0; nt < 4; nt++) {
                size_t idx = rowbase + n0 + nW + nt * 8 + cc;
                float v0 = acc[mt][nt][half * 2 + 0];
                float v1 = acc[mt][nt][half * 2 + 1];
                if (MODE == 0) {
                    *(float2*)&g_g[idx] = make_float2(v0, v1);
                } else if (MODE == 1) {
                    float2 gg = *(const float2*)&g_g[idx];
                    float h0 = v0 * (gg.x / (1.f + expf(-gg.x)));
                    float h1 = v1 * (gg.y / (1.f + expf(-gg.y)));
                    uint2 hh;
                    hh.x = tf32r(h0); hh.y = tf32r(h1);
                    *(uint2*)&g_h[idx] = hh;
                } else {
                    *(float2*)&g_y[idx] = make_float2(v0 * wt, v1 * wt);
                }
            }
        }
    }
}

__global__ __launch_bounds__(256) void combine_kernel(float* __restrict__ out)
{
    int t = blockIdx.x;
    int e0 = g_tok_e[t][0], e1 = g_tok_e[t][1];
    int s0 = g_off[e0] + g_tok_p[t][0];
    int s1 = g_off[e1] + g_tok_p[t][1];
    const float4* y0 = (const float4*)(g_y + (size_t)s0 * HDIM);
    const float4* y1 = (const float4*)(g_y + (size_t)s1 * HDIM);
    float4* o = (float4*)(out + (size_t)t * HDIM);
    for (int h = threadIdx.x; h < HDIM / 4; h += blockDim.x) {
        float4 a = y0[h], b = y1[h];
        o[h] = make_float4(a.x + b.x, a.y + b.y, a.z + b.z, a.w + b.w);
    }
}

extern "C" void kernel_launch(void* const* d_in, const int* in_sizes, int n_in,
                              void* d_out, int out_size)
{
    const float* x        = (const float*)d_in[0];
    const float* norm_w   = (const float*)d_in[1];
    const float* router_w = (const float*)d_in[2];
    const float* w_gate   = (const float*)d_in[3];
    const float* w_up     = (const float*)d_in[4];
    const float* w_down   = (const float*)d_in[5];
    float* out = (float*)d_out;

    cudaFuncSetAttribute(moe_mma_gemm<0>, cudaFuncAttributeMaxDynamicSharedMemorySize, SMEM_DYN);
    cudaFuncSetAttribute(moe_mma_gemm<1>, cudaFuncAttributeMaxDynamicSharedMemorySize, SMEM_DYN);
    cudaFuncSetAttribute(moe_mma_gemm<2>, cudaFuncAttributeMaxDynamicSharedMemorySize, SMEM_DYN);

    zero_cnt_kernel<<<1, 32>>>();
    norm_route_kernel<<<TTOK, 256>>>(x, norm_w, router_w);
    prefix_kernel<<<1, 1>>>();
    moe_mma_gemm<0><<<dim3(IDIM / BN, TTOK / BM, EEXP), 256, SMEM_DYN>>>(w_gate);
    moe_mma_gemm<1><<<dim3(IDIM / BN, TTOK / BM, EEXP), 256, SMEM_DYN>>>(w_up);
    moe_mma_gemm<2><<<dim3(HDIM / BN, TTOK / BM, EEXP), 256, SMEM_DYN>>>(w_down);
    combine_kernel<<<TTOK, 256>>>(out);
}

// round 14
// speedup vs baseline: 5.0243x; 1.3297x over previous
#include <cuda_runtime.h>
#include <cuda_fp16.h>
#include <cstdint>
#include <math.h>

#define TTOK 2048
#define HDIM 2048
#define IDIM 4096
#define EEXP 8
#define KTOP 2

// ---------------- scratch (device globals; no allocation allowed) ----------
__device__ __half g_tnh[(size_t)TTOK * HDIM];        // normalized tokens (fp16)
__device__ int    g_cnt[EEXP];
__device__ int    g_off[EEXP];
__device__ int    g_tok[EEXP][TTOK];
__device__ float  g_wt [EEXP][TTOK];
__device__ int    g_tok_e[TTOK][KTOP];
__device__ int    g_tok_p[TTOK][KTOP];
__device__ float  g_g[(size_t)TTOK * KTOP * IDIM];   // gate preact (fp32)
__device__ __half g_hh[(size_t)TTOK * KTOP * IDIM];  // silu(g)*u (fp16)
__device__ float  g_y[(size_t)TTOK * KTOP * HDIM];   // weighted down-proj out

__device__ __forceinline__ uint32_t packh2(float lo, float hi) {
    uint32_t d;   // cvt d, a, b -> hi half = cvt(a), lo half = cvt(b)
    asm("cvt.rn.f16x2.f32 %0, %1, %2;" : "=r"(d) : "f"(hi), "f"(lo));
    return d;
}

__device__ __forceinline__ void mma_f16(float* c, const uint32_t* a, const uint32_t* b) {
    asm volatile(
        "mma.sync.aligned.m16n8k16.row.col.f32.f16.f16.f32 "
        "{%0,%1,%2,%3}, {%4,%5,%6,%7}, {%8,%9}, {%0,%1,%2,%3};"
        : "+f"(c[0]), "+f"(c[1]), "+f"(c[2]), "+f"(c[3])
        : "r"(a[0]), "r"(a[1]), "r"(a[2]), "r"(a[3]), "r"(b[0]), "r"(b[1]));
}

__device__ __forceinline__ uint32_t smem_u32(const void* p) {
    uint32_t a;
    asm("{ .reg .u64 t; cvta.to.shared.u64 t, %1; cvt.u32.u64 %0, t; }" : "=r"(a) : "l"(p));
    return a;
}
__device__ __forceinline__ void cp_async16(uint32_t dst, const void* src) {
    asm volatile("cp.async.cg.shared.global [%0], [%1], 16;" :: "r"(dst), "l"(src));
}
#define CP_COMMIT() asm volatile("cp.async.commit_group;" ::: "memory")
#define CP_WAIT2()  asm volatile("cp.async.wait_group 2;"  ::: "memory")
#define CP_WAIT1()  asm volatile("cp.async.wait_group 1;"  ::: "memory")
#define CP_WAIT0()  asm volatile("cp.async.wait_group 0;"  ::: "memory")

// ---------------- small kernels --------------------------------------------
__global__ void zero_cnt_kernel() { if (threadIdx.x < EEXP) g_cnt[threadIdx.x] = 0; }

__global__ void prefix_kernel() {
    int r = 0;
    for (int e = 0; e < EEXP; e++) { g_off[e] = r; r += g_cnt[e]; }
}

__global__ __launch_bounds__(256) void norm_route_kernel(
    const float* __restrict__ x, const float* __restrict__ norm_w,
    const float* __restrict__ router_w)
{
    int t = blockIdx.x, tid = threadIdx.x;
    __shared__ float s_tn[HDIM];
    __shared__ float s_red[8];
    __shared__ float s_logit[EEXP];

    const float* xr = x + (size_t)t * HDIM;
    float v[8]; float ss = 0.f;
    #pragma unroll
    for (int i = 0; i < 8; i++) { float xv = xr[tid + i * 256]; v[i] = xv; ss += xv * xv; }
    #pragma unroll
    for (int o = 16; o; o >>= 1) ss += __shfl_xor_sync(0xffffffffu, ss, o);
    if ((tid & 31) == 0) s_red[tid >> 5] = ss;
    __syncthreads();
    if (tid < 8) {
        float r = s_red[tid];
        #pragma unroll
        for (int o = 4; o; o >>= 1) r += __shfl_xor_sync(0xffu, r, o);
        if (tid == 0) s_red[0] = r;
    }
    __syncthreads();
    float inv = rsqrtf(s_red[0] * (1.0f / HDIM) + 1e-6f);
    #pragma unroll
    for (int i = 0; i < 8; i++) {
        int h = tid + i * 256;
        float tnv = v[i] * inv * norm_w[h];
        s_tn[h] = tnv;
        g_tnh[(size_t)t * HDIM + h] = __float2half_rn(tnv);  // A operand, fp16-rn once
    }
    __syncthreads();

    int e = tid >> 5, lane = tid & 31;
    float lg = 0.f;
    for (int h = lane; h < HDIM; h += 32) lg += s_tn[h] * router_w[h * EEXP + e];
    #pragma unroll
    for (int o = 16; o; o >>= 1) lg += __shfl_xor_sync(0xffffffffu, lg, o);
    if (lane == 0) s_logit[e] = lg;
    __syncthreads();

    if (tid == 0) {
        float mx = -1e30f;
        #pragma unroll
        for (int i = 0; i < EEXP; i++) mx = fmaxf(mx, s_logit[i]);
        float p[EEXP];
        #pragma unroll
        for (int i = 0; i < EEXP; i++) p[i] = expf(s_logit[i] - mx);
        int i0 = 0;
        #pragma unroll
        for (int i = 1; i < EEXP; i++) if (p[i] > p[i0]) i0 = i;
        int i1 = (i0 == 0) ? 1 : 0;
        #pragma unroll
        for (int i = 0; i < EEXP; i++) { if (i != i0 && p[i] > p[i1]) i1 = i; }
        float v0 = p[i0], v1 = p[i1], wsum = v0 + v1;
        int p0 = atomicAdd(&g_cnt[i0], 1);
        int p1 = atomicAdd(&g_cnt[i1], 1);
        g_tok[i0][p0] = t;  g_wt[i0][p0] = v0 / wsum;
        g_tok[i1][p1] = t;  g_wt[i1][p1] = v1 / wsum;
        g_tok_e[t][0] = i0; g_tok_p[t][0] = p0;
        g_tok_e[t][1] = i1; g_tok_p[t][1] = p1;
    }
}

// ---------------- fp16 mma.sync grouped GEMM, 4-stage cp.async --------------
// MODE 0: A=g_tnh(gather) B=w_gate[e] [H,I]  -> g_g             (K=H, N=I)
// MODE 1: A=g_tnh(gather) B=w_up[e]   [H,I]  -> g_hh=silu(g)*u  (K=H, N=I)
// MODE 2: A=g_hh rows     B=w_down[e] [I,H]  -> g_y=wt*(h@Wd)   (K=I, N=H)
#define BM  128
#define BN  128
#define BK  32
#define APADH 40    // fp16/row: 80B = 16 mod 128 -> banks 20r+tig all-distinct
#define BPADF 132   // fp32/row: stride 4 banks -> fragment rows conflict-free
#define STAGES 4

#define SZ_A_BYTES (BM * APADH * 2)      // 10240
#define SZ_B_BYTES (BK * BPADF * 4)      // 16896
#define A_REGION   (STAGES * SZ_A_BYTES) // 40960
#define SMEM_DYN   (A_REGION + STAGES * SZ_B_BYTES)  // 108544

template<int MODE>
__global__ __launch_bounds__(256, 2) void moe_mma_gemm(const float* __restrict__ W)
{
    constexpr int KD = (MODE == 2) ? IDIM : HDIM;
    constexpr int ND = (MODE == 2) ? HDIM : IDIM;
    constexpr int NC = KD / BK;

    int e   = blockIdx.z;
    int cnt = g_cnt[e];
    int m0  = blockIdx.y * BM;
    if (m0 >= cnt) return;
    int n0  = blockIdx.x * BN;
    int off = g_off[e];
    const float* Wb = W + (size_t)e * KD * ND;

    extern __shared__ char dsm[];
    uint32_t sAu0 = smem_u32(dsm);
    uint32_t sBu0 = sAu0 + A_REGION;
    const float* dBf = (const float*)(dsm + A_REGION);

    __shared__ const __half* s_aptr[BM];

    int tid  = threadIdx.x;
    int wid  = tid >> 5, lane = tid & 31;
    int mW   = (wid >> 2) * 64;              // warp m-offset (2 warps in M)
    int nW   = (wid & 3) * 32;               // warp n-offset (4 warps in N)
    int gid  = lane >> 2, tig = lane & 3;

    {
        int m = m0 + (tid >> 1);
        if ((tid & 1) == 0) {
            const __half* p;
            if (MODE == 2) p = g_hh + (size_t)(off + ((m < cnt) ? m : 0)) * IDIM;
            else           p = g_tnh + (size_t)g_tok[e][(m < cnt) ? m : 0] * HDIM;
            s_aptr[tid >> 1] = p;   // invalid rows alias row 0; never stored
        }
    }
    __syncthreads();

    float acc[4][4][4];
    #pragma unroll
    for (int i = 0; i < 4; i++)
        #pragma unroll
        for (int j = 0; j < 4; j++)
            #pragma unroll
            for (int k = 0; k < 4; k++) acc[i][j][k] = 0.f;

    // ---- stage issue: A (2x cp.async, fp16) + B (4x cp.async, fp32) -------
    auto issueAB = [&](int stage, int k0) {
        #pragma unroll
        for (int it = 0; it < 2; it++) {
            int f = tid + it * 256;
            int row = f >> 2, c8 = f & 3;    // 4x 16B (8 fp16) per 32-elem row
            cp_async16(sAu0 + (uint32_t)(stage * SZ_A_BYTES + row * (APADH * 2) + c8 * 16),
                       s_aptr[row] + k0 + c8 * 8);
        }
        #pragma unroll
        for (int it = 0; it < 4; it++) {
            int f = tid + it * 256;
            int k = f >> 5, pn = f & 31;
            cp_async16(sBu0 + (uint32_t)(stage * SZ_B_BYTES + (k * BPADF + pn * 4) * 4),
                       Wb + (size_t)(k0 + k) * ND + n0 + pn * 4);
        }
        CP_COMMIT();
    };

    // ---- prologue: 3 stages in flight ----
    issueAB(0, 0);
    issueAB(1, BK);
    issueAB(2, 2 * BK);

    for (int c = 0; c < NC; c++) {
        int pend = NC - 1 - c;   // younger groups issued beyond chunk c
        if (pend >= 2) CP_WAIT2();
        else if (pend == 1) CP_WAIT1();
        else CP_WAIT0();
        __syncthreads();
        if (c + 3 < NC) issueAB((c + 3) % STAGES, (c + 3) * BK);

        const uint32_t* sAc = (const uint32_t*)(dsm + (c % STAGES) * SZ_A_BYTES);
        const float*    sBc = dBf + (c % STAGES) * (SZ_B_BYTES / 4);

        #pragma unroll
        for (int ks = 0; ks < 2; ks++) {     // two k16 steps per BK=32 chunk
            uint32_t af[4][4], bf[4][2];
            int akw = ks * 8 + tig;          // u32 index of fp16x2 pair in row
            #pragma unroll
            for (int mt = 0; mt < 4; mt++) {
                int r = mW + gid + mt * 16;
                af[mt][0] = sAc[(size_t)r * (APADH / 2) + akw];
                af[mt][1] = sAc[(size_t)(r + 8) * (APADH / 2) + akw];
                af[mt][2] = sAc[(size_t)r * (APADH / 2) + akw + 4];
                af[mt][3] = sAc[(size_t)(r + 8) * (APADH / 2) + akw + 4];
            }
            int kb = ks * 16 + tig * 2;
            #pragma unroll
            for (int nt = 0; nt < 4; nt++) {
                int n = nW + gid + nt * 8;
                bf[nt][0] = packh2(sBc[(size_t)kb * BPADF + n],
                                   sBc[(size_t)(kb + 1) * BPADF + n]);
                bf[nt][1] = packh2(sBc[(size_t)(kb + 8) * BPADF + n],
                                   sBc[(size_t)(kb + 9) * BPADF + n]);
            }
            #pragma unroll
            for (int mt = 0; mt < 4; mt++)
                #pragma unroll
                for (int nt = 0; nt < 4; nt++)
                    mma_f16(acc[mt][nt], af[mt], bf[nt]);
        }
    }

    // ---- epilogue (C fragment layout identical to tf32 path) ----
    int rr = gid, cc = tig * 2;
    #pragma unroll
    for (int mt = 0; mt < 4; mt++) {
        #pragma unroll
        for (int half = 0; half < 2; half++) {
            int m = m0 + mW + mt * 16 + rr + half * 8;
            if (m >= cnt) continue;
            size_t rowbase = (size_t)(off + m) * ND;
            float wt = (MODE == 2) ? g_wt[e][m] : 0.f;
            #pragma unroll
            for (int nt = 0; nt < 4; nt++) {
                size_t idx = rowbase + n0 + nW + nt * 8 + cc;
                float v0 = acc[mt][nt][half * 2 + 0];
                float v1 = acc[mt][nt][half * 2 + 1];
                if (MODE == 0) {
                    *(float2*)&g_g[idx] = make_float2(v0, v1);
                } else if (MODE == 1) {
                    float2 gg = *(const float2*)&g_g[idx];
                    float h0 = v0 * (gg.x / (1.f + expf(-gg.x)));
                    float h1 = v1 * (gg.y / (1.f + expf(-gg.y)));
                    *(uint32_t*)&g_hh[idx] = packh2(h0, h1);
                } else {
                    *(float2*)&g_y[idx] = make_float2(v0 * wt, v1 * wt);
                }
            }
        }
    }
}

__global__ __launch_bounds__(256) void combine_kernel(float* __restrict__ out)
{
    int t = blockIdx.x;
    int e0 = g_tok_e[t][0], e1 = g_tok_e[t][1];
    int s0 = g_off[e0] + g_tok_p[t][0];
    int s1 = g_off[e1] + g_tok_p[t][1];
    const float4* y0 = (const float4*)(g_y + (size_t)s0 * HDIM);
    const float4* y1 = (const float4*)(g_y + (size_t)s1 * HDIM);
    float4* o = (float4*)(out + (size_t)t * HDIM);
    for (int h = threadIdx.x; h < HDIM / 4; h += blockDim.x) {
        float4 a = y0[h], b = y1[h];
        o[h] = make_float4(a.x + b.x, a.y + b.y, a.z + b.z, a.w + b.w);
    }
}

extern "C" void kernel_launch(void* const* d_in, const int* in_sizes, int n_in,
                              void* d_out, int out_size)
{
    const float* x        = (const float*)d_in[0];
    const float* norm_w   = (const float*)d_in[1];
    const float* router_w = (const float*)d_in[2];
    const float* w_gate   = (const float*)d_in[3];
    const float* w_up     = (const float*)d_in[4];
    const float* w_down   = (const float*)d_in[5];
    float* out = (float*)d_out;

    cudaFuncSetAttribute(moe_mma_gemm<0>, cudaFuncAttributeMaxDynamicSharedMemorySize, SMEM_DYN);
    cudaFuncSetAttribute(moe_mma_gemm<1>, cudaFuncAttributeMaxDynamicSharedMemorySize, SMEM_DYN);
    cudaFuncSetAttribute(moe_mma_gemm<2>, cudaFuncAttributeMaxDynamicSharedMemorySize, SMEM_DYN);

    zero_cnt_kernel<<<1, 32>>>();
    norm_route_kernel<<<TTOK, 256>>>(x, norm_w, router_w);
    prefix_kernel<<<1, 1>>>();
    moe_mma_gemm<0><<<dim3(IDIM / BN, TTOK / BM, EEXP), 256, SMEM_DYN>>>(w_gate);
    moe_mma_gemm<1><<<dim3(IDIM / BN, TTOK / BM, EEXP), 256, SMEM_DYN>>>(w_up);
    moe_mma_gemm<2><<<dim3(HDIM / BN, TTOK / BM, EEXP), 256, SMEM_DYN>>>(w_down);
    combine_kernel<<<TTOK, 256>>>(out);
}

// round 16
// speedup vs baseline: 5.6435x; 1.1232x over previous
#include <cuda_runtime.h>
#include <cuda_fp16.h>
#include <cstdint>
#include <math.h>

#define TTOK 2048
#define HDIM 2048
#define IDIM 4096
#define EEXP 8
#define KTOP 2

// ---------------- scratch (device globals; no allocation allowed) ----------
__device__ __half g_tnh[(size_t)TTOK * HDIM];        // normalized tokens (fp16)
__device__ int    g_cnt[EEXP];
__device__ int    g_off[EEXP];
__device__ int    g_tok[EEXP][TTOK];
__device__ float  g_wt [EEXP][TTOK];
__device__ int    g_tok_e[TTOK][KTOP];
__device__ int    g_tok_p[TTOK][KTOP];
__device__ float  g_g[(size_t)TTOK * KTOP * IDIM];   // gate preact (fp32)
__device__ __half g_hh[(size_t)TTOK * KTOP * IDIM];  // silu(g)*u (fp16)
__device__ float  g_y[(size_t)TTOK * KTOP * HDIM];   // weighted down-proj out
// fp16 weight mirrors (rn-rounded once per launch; identical rounding to packh2)
__device__ __half g_wg_h[(size_t)EEXP * HDIM * IDIM];
__device__ __half g_wu_h[(size_t)EEXP * HDIM * IDIM];
__device__ __half g_wd_h[(size_t)EEXP * IDIM * HDIM];

__device__ __forceinline__ uint32_t packh2(float lo, float hi) {
    uint32_t d;
    asm("cvt.rn.f16x2.f32 %0, %1, %2;" : "=r"(d) : "f"(hi), "f"(lo));
    return d;
}

__device__ __forceinline__ void mma_f16(float* c, const uint32_t* a, const uint32_t* b) {
    asm volatile(
        "mma.sync.aligned.m16n8k16.row.col.f32.f16.f16.f32 "
        "{%0,%1,%2,%3}, {%4,%5,%6,%7}, {%8,%9}, {%0,%1,%2,%3};"
        : "+f"(c[0]), "+f"(c[1]), "+f"(c[2]), "+f"(c[3])
        : "r"(a[0]), "r"(a[1]), "r"(a[2]), "r"(a[3]), "r"(b[0]), "r"(b[1]));
}

__device__ __forceinline__ void ldsm_x4(uint32_t* r, uint32_t addr) {
    asm volatile("ldmatrix.sync.aligned.m8n8.x4.shared.b16 {%0,%1,%2,%3}, [%4];"
        : "=r"(r[0]), "=r"(r[1]), "=r"(r[2]), "=r"(r[3]) : "r"(addr));
}
__device__ __forceinline__ void ldsm_x2t(uint32_t* r, uint32_t addr) {
    asm volatile("ldmatrix.sync.aligned.m8n8.x2.trans.shared.b16 {%0,%1}, [%2];"
        : "=r"(r[0]), "=r"(r[1]) : "r"(addr));
}

__device__ __forceinline__ uint32_t smem_u32(const void* p) {
    uint32_t a;
    asm("{ .reg .u64 t; cvta.to.shared.u64 t, %1; cvt.u32.u64 %0, t; }" : "=r"(a) : "l"(p));
    return a;
}
__device__ __forceinline__ void cp_async16(uint32_t dst, const void* src) {
    asm volatile("cp.async.cg.shared.global [%0], [%1], 16;" :: "r"(dst), "l"(src));
}
#define CP_COMMIT() asm volatile("cp.async.commit_group;" ::: "memory")
#define CP_WAIT1()  asm volatile("cp.async.wait_group 1;"  ::: "memory")
#define CP_WAIT0()  asm volatile("cp.async.wait_group 0;"  ::: "memory")

// ---------------- small kernels --------------------------------------------
__global__ void zero_cnt_kernel() { if (threadIdx.x < EEXP) g_cnt[threadIdx.x] = 0; }

__global__ void prefix_kernel() {
    int r = 0;
    for (int e = 0; e < EEXP; e++) { g_off[e] = r; r += g_cnt[e]; }
}

// fp32 -> fp16 weight conversion (pure bandwidth; float4 -> 2x half2)
__global__ __launch_bounds__(256) void cvt_w_kernel(const float* __restrict__ src,
                                                    __half* __restrict__ dst, int n4) {
    int i = blockIdx.x * blockDim.x + threadIdx.x;
    if (i < n4) {
        float4 v = ((const float4*)src)[i];
        uint32_t lo = packh2(v.x, v.y);
        uint32_t hi = packh2(v.z, v.w);
        ((uint2*)dst)[i] = make_uint2(lo, hi);
    }
}

__global__ __launch_bounds__(256) void norm_route_kernel(
    const float* __restrict__ x, const float* __restrict__ norm_w,
    const float* __restrict__ router_w)
{
    int t = blockIdx.x, tid = threadIdx.x;
    __shared__ float s_tn[HDIM];
    __shared__ float s_red[8];
    __shared__ float s_logit[EEXP];

    const float* xr = x + (size_t)t * HDIM;
    float v[8]; float ss = 0.f;
    #pragma unroll
    for (int i = 0; i < 8; i++) { float xv = xr[tid + i * 256]; v[i] = xv; ss += xv * xv; }
    #pragma unroll
    for (int o = 16; o; o >>= 1) ss += __shfl_xor_sync(0xffffffffu, ss, o);
    if ((tid & 31) == 0) s_red[tid >> 5] = ss;
    __syncthreads();
    if (tid < 8) {
        float r = s_red[tid];
        #pragma unroll
        for (int o = 4; o; o >>= 1) r += __shfl_xor_sync(0xffu, r, o);
        if (tid == 0) s_red[0] = r;
    }
    __syncthreads();
    float inv = rsqrtf(s_red[0] * (1.0f / HDIM) + 1e-6f);
    #pragma unroll
    for (int i = 0; i < 8; i++) {
        int h = tid + i * 256;
        float tnv = v[i] * inv * norm_w[h];
        s_tn[h] = tnv;
        g_tnh[(size_t)t * HDIM + h] = __float2half_rn(tnv);
    }
    __syncthreads();

    int e = tid >> 5, lane = tid & 31;
    float lg = 0.f;
    for (int h = lane; h < HDIM; h += 32) lg += s_tn[h] * router_w[h * EEXP + e];
    #pragma unroll
    for (int o = 16; o; o >>= 1) lg += __shfl_xor_sync(0xffffffffu, lg, o);
    if (lane == 0) s_logit[e] = lg;
    __syncthreads();

    if (tid == 0) {
        float mx = -1e30f;
        #pragma unroll
        for (int i = 0; i < EEXP; i++) mx = fmaxf(mx, s_logit[i]);
        float p[EEXP];
        #pragma unroll
        for (int i = 0; i < EEXP; i++) p[i] = expf(s_logit[i] - mx);
        int i0 = 0;
        #pragma unroll
        for (int i = 1; i < EEXP; i++) if (p[i] > p[i0]) i0 = i;
        int i1 = (i0 == 0) ? 1 : 0;
        #pragma unroll
        for (int i = 0; i < EEXP; i++) { if (i != i0 && p[i] > p[i1]) i1 = i; }
        float v0 = p[i0], v1 = p[i1], wsum = v0 + v1;
        int p0 = atomicAdd(&g_cnt[i0], 1);
        int p1 = atomicAdd(&g_cnt[i1], 1);
        g_tok[i0][p0] = t;  g_wt[i0][p0] = v0 / wsum;
        g_tok[i1][p1] = t;  g_wt[i1][p1] = v1 / wsum;
        g_tok_e[t][0] = i0; g_tok_p[t][0] = p0;
        g_tok_e[t][1] = i1; g_tok_p[t][1] = p1;
    }
}

// ---------------- fp16 mma.sync grouped GEMM, ldmatrix + 3-stage ------------
// MODE 0: A=g_tnh(gather) B=g_wg_h[e] [H,I]  -> g_g             (K=H, N=I)
// MODE 1: A=g_tnh(gather) B=g_wu_h[e] [H,I]  -> g_hh=silu(g)*u  (K=H, N=I)
// MODE 2: A=g_hh rows     B=g_wd_h[e] [I,H]  -> g_y=wt*(h@Wd)   (K=I, N=H)
#define BM  128
#define BN  128
#define BK  64
#define A_ROW_B 144   // 64+8 fp16 per row; 144 % 128 = 16 -> LDSM phases conflict-free
#define B_ROW_B 272   // 128+8 fp16 per row; 272 % 128 = 16 -> conflict-free
#define STAGES 3

#define SZ_A_BYTES (BM * A_ROW_B)        // 18432
#define SZ_B_BYTES (BK * B_ROW_B)        // 17408
#define A_REGION   (STAGES * SZ_A_BYTES) // 55296
#define SMEM_DYN   (A_REGION + STAGES * SZ_B_BYTES)  // 107520

template<int MODE>
__global__ __launch_bounds__(256, 2) void moe_mma_gemm(const __half* __restrict__ Wh)
{
    constexpr int KD = (MODE == 2) ? IDIM : HDIM;
    constexpr int ND = (MODE == 2) ? HDIM : IDIM;
    constexpr int NC = KD / BK;

    int e   = blockIdx.z;
    int cnt = g_cnt[e];
    int m0  = blockIdx.y * BM;
    if (m0 >= cnt) return;
    int n0  = blockIdx.x * BN;
    int off = g_off[e];
    const __half* Wb = Wh + (size_t)e * KD * ND;

    extern __shared__ char dsm[];
    uint32_t sAu0 = smem_u32(dsm);
    uint32_t sBu0 = sAu0 + A_REGION;

    __shared__ const __half* s_aptr[BM];

    int tid  = threadIdx.x;
    int wid  = tid >> 5, lane = tid & 31;
    int mW   = (wid >> 2) * 64;              // warp m-offset (2 warps in M)
    int nW   = (wid & 3) * 32;               // warp n-offset (4 warps in N)
    int gid  = lane >> 2, tig = lane & 3;

    {
        int m = m0 + (tid >> 1);
        if ((tid & 1) == 0) {
            const __half* p;
            if (MODE == 2) p = g_hh + (size_t)(off + ((m < cnt) ? m : 0)) * IDIM;
            else           p = g_tnh + (size_t)g_tok[e][(m < cnt) ? m : 0] * HDIM;
            s_aptr[tid >> 1] = p;   // invalid rows alias row 0; never stored
        }
    }
    __syncthreads();

    float acc[4][4][4];
    #pragma unroll
    for (int i = 0; i < 4; i++)
        #pragma unroll
        for (int j = 0; j < 4; j++)
            #pragma unroll
            for (int k = 0; k < 4; k++) acc[i][j][k] = 0.f;

    // ---- stage issue: A 4x + B 4x cp.async (16B each), one commit group ----
    auto issueAB = [&](int stage, int k0) {
        #pragma unroll
        for (int it = 0; it < 4; it++) {
            int f = tid + it * 256;          // f < 1024
            int row = f >> 3, c8 = f & 7;    // 8x 16B (8 fp16) per 64-elem row
            cp_async16(sAu0 + (uint32_t)(stage * SZ_A_BYTES + row * A_ROW_B + c8 * 16),
                       s_aptr[row] + k0 + c8 * 8);
        }
        #pragma unroll
        for (int it = 0; it < 4; it++) {
            int f = tid + it * 256;          // f < 1024
            int k = f >> 4, u = f & 15;      // 16x 16B per 128-elem row
            cp_async16(sBu0 + (uint32_t)(stage * SZ_B_BYTES + k * B_ROW_B + u * 16),
                       Wb + (size_t)(k0 + k) * ND + n0 + u * 8);
        }
        CP_COMMIT();
    };

    // per-lane ldmatrix base offsets
    //  A (x4):  lanes 0-7 m0 rows r..r+7 k0-7 | 8-15 rows +8 | 16-23 k+8 | 24-31 rows+8,k+8
    uint32_t a_lane = (uint32_t)((mW + (lane & 7) + ((lane >> 3) & 1) * 8) * A_ROW_B
                                 + ((lane >> 4) * 8) * 2);
    //  B (x2.trans): lanes 0-15 -> k rows kb+0..15 (others ignored, keep valid)
    uint32_t b_lane = (uint32_t)((lane & 15) * B_ROW_B);

    // ---- prologue: stages 0 and 1 in flight ----
    issueAB(0, 0);
    issueAB(1, BK);

    for (int c = 0; c < NC; c++) {
        if (c + 1 < NC) CP_WAIT1(); else CP_WAIT0();
        __syncthreads();
        if (c + 2 < NC) issueAB((c + 2) % STAGES, (c + 2) * BK);

        uint32_t sA0 = sAu0 + (uint32_t)((c % STAGES) * SZ_A_BYTES);
        uint32_t sB0 = sBu0 + (uint32_t)((c % STAGES) * SZ_B_BYTES);

        #pragma unroll
        for (int ks = 0; ks < 4; ks++) {     // four k16 steps per BK=64 chunk
            uint32_t af[4][4], bf[4][2];
            #pragma unroll
            for (int mt = 0; mt < 4; mt++)
                ldsm_x4(af[mt], sA0 + a_lane + (uint32_t)(mt * 16 * A_ROW_B + ks * 32));
            #pragma unroll
            for (int nt = 0; nt < 4; nt++)
                ldsm_x2t(bf[nt], sB0 + b_lane + (uint32_t)(ks * 16 * B_ROW_B + (nW + nt * 8) * 2));
            #pragma unroll
            for (int mt = 0; mt < 4; mt++)
                #pragma unroll
                for (int nt = 0; nt < 4; nt++)
                    mma_f16(acc[mt][nt], af[mt], bf[nt]);
        }
    }

    // ---- epilogue (C fragment layout unchanged) ----
    int rr = gid, cc = tig * 2;
    #pragma unroll
    for (int mt = 0; mt < 4; mt++) {
        #pragma unroll
        for (int half = 0; half < 2; half++) {
            int m = m0 + mW + mt * 16 + rr + half * 8;
            if (m >= cnt) continue;
            size_t rowbase = (size_t)(off + m) * ND;
            float wt = (MODE == 2) ? g_wt[e][m] : 0.f;
            #pragma unroll
            for (int nt = 0; nt < 4; nt++) {
                size_t idx = rowbase + n0 + nW + nt * 8 + cc;
                float v0 = acc[mt][nt][half * 2 + 0];
                float v1 = acc[mt][nt][half * 2 + 1];
                if (MODE == 0) {
                    *(float2*)&g_g[idx] = make_float2(v0, v1);
                } else if (MODE == 1) {
                    float2 gg = *(const float2*)&g_g[idx];
                    float h0 = v0 * (gg.x / (1.f + expf(-gg.x)));
                    float h1 = v1 * (gg.y / (1.f + expf(-gg.y)));
                    *(uint32_t*)&g_hh[idx] = packh2(h0, h1);
                } else {
                    *(float2*)&g_y[idx] = make_float2(v0 * wt, v1 * wt);
                }
            }
        }
    }
}

__global__ __launch_bounds__(256) void combine_kernel(float* __restrict__ out)
{
    int t = blockIdx.x;
    int e0 = g_tok_e[t][0], e1 = g_tok_e[t][1];
    int s0 = g_off[e0] + g_tok_p[t][0];
    int s1 = g_off[e1] + g_tok_p[t][1];
    const float4* y0 = (const float4*)(g_y + (size_t)s0 * HDIM);
    const float4* y1 = (const float4*)(g_y + (size_t)s1 * HDIM);
    float4* o = (float4*)(out + (size_t)t * HDIM);
    for (int h = threadIdx.x; h < HDIM / 4; h += blockDim.x) {
        float4 a = y0[h], b = y1[h];
        o[h] = make_float4(a.x + b.x, a.y + b.y, a.z + b.z, a.w + b.w);
    }
}

extern "C" void kernel_launch(void* const* d_in, const int* in_sizes, int n_in,
                              void* d_out, int out_size)
{
    const float* x        = (const float*)d_in[0];
    const float* norm_w   = (const float*)d_in[1];
    const float* router_w = (const float*)d_in[2];
    const float* w_gate   = (const float*)d_in[3];
    const float* w_up     = (const float*)d_in[4];
    const float* w_down   = (const float*)d_in[5];
    float* out = (float*)d_out;

    cudaFuncSetAttribute(moe_mma_gemm<0>, cudaFuncAttributeMaxDynamicSharedMemorySize, SMEM_DYN);
    cudaFuncSetAttribute(moe_mma_gemm<1>, cudaFuncAttributeMaxDynamicSharedMemorySize, SMEM_DYN);
    cudaFuncSetAttribute(moe_mma_gemm<2>, cudaFuncAttributeMaxDynamicSharedMemorySize, SMEM_DYN);

    // weight fp16 mirrors (rn rounding, identical to previous packh2-at-use)
    __half *wg_h, *wu_h, *wd_h;
    cudaGetSymbolAddress((void**)&wg_h, g_wg_h);
    cudaGetSymbolAddress((void**)&wu_h, g_wu_h);
    cudaGetSymbolAddress((void**)&wd_h, g_wd_h);
    const int n4 = EEXP * HDIM * IDIM / 4;   // 16,777,216
    cvt_w_kernel<<<(n4 + 255) / 256, 256>>>(w_gate, wg_h, n4);
    cvt_w_kernel<<<(n4 + 255) / 256, 256>>>(w_up,   wu_h, n4);
    cvt_w_kernel<<<(n4 + 255) / 256, 256>>>(w_down, wd_h, n4);

    zero_cnt_kernel<<<1, 32>>>();
    norm_route_kernel<<<TTOK, 256>>>(x, norm_w, router_w);
    prefix_kernel<<<1, 1>>>();
    moe_mma_gemm<0><<<dim3(IDIM / BN, TTOK / BM, EEXP), 256, SMEM_DYN>>>(wg_h);
    moe_mma_gemm<1><<<dim3(IDIM / BN, TTOK / BM, EEXP), 256, SMEM_DYN>>>(wu_h);
    moe_mma_gemm<2><<<dim3(HDIM / BN, TTOK / BM, EEXP), 256, SMEM_DYN>>>(wd_h);
    combine_kernel<<<TTOK, 256>>>(out);
}